// round 17
// baseline (speedup 1.0000x reference)
#include <cuda_runtime.h>
#include <cuda_bf16.h>
#include <cstdint>

// Problem constants (fixed by the reference)
#define NB 32      // batch
#define NZ 4000    // nodes
#define NIN 32     // in features
#define NH 64      // hidden
#define NE 64000   // edges

#define NY  (NB * NZ * NIN / 4)   // 1,024,000 float4 loads of x
#define NYB (NY / 1024)           // 1000 ydot blocks (1024 float4 per block)
#define NEB (NE / 256)            // 250 histogram blocks
#define NSB ((NE * 8) / 512)      // 1000 scatter blocks (2 float4 REDs/thread)

// Scratch (device globals; zero-initialized at module load).
// g_acc is zero-initialized by k_ydot_hist each execution (before K3 adds);
// g_deg is re-zeroed by k_out after use.
__device__ __align__(16) float g_y[NZ * NB];    // y[z*NB+b] = x[b,z,:] . v (RAW)
__device__ __align__(16) float g_acc[NZ * NB];  // acc[z][b] = sum_{s->z} dinv_s*y_s
__device__ int g_deg[NZ];                       // in-degree EXCLUDING self-loop
__device__ __align__(16) float g_v[NIN];        // W @ fc_W
__device__ float g_const;                       // bias . fc_W + fc_b

// ---------------------------------------------------------------------------
// K1: v = W @ fc_W and const = bias . fc_W + fc_b. ONE block — this is the
// only thing the ydot stream truly depends on, so keep the serial stage tiny.
// ---------------------------------------------------------------------------
__global__ void k_v(const float* __restrict__ W,
                    const float* __restrict__ bias,
                    const float* __restrict__ fcW,
                    const float* __restrict__ fcb) {
    const int tx = threadIdx.x;
    // v[i] = sum_h W[i*NH+h]*fcW[h]; thread (i = tx>>3, j = tx&7)
    int i = tx >> 3;
    int j = tx & 7;
    float p = 0.f;
    #pragma unroll
    for (int k = 0; k < 8; ++k)
        p += W[i * NH + j * 8 + k] * fcW[j * 8 + k];
    p += __shfl_xor_sync(0xFFFFFFFFu, p, 1);
    p += __shfl_xor_sync(0xFFFFFFFFu, p, 2);
    p += __shfl_xor_sync(0xFFFFFFFFu, p, 4);
    if (j == 0) g_v[i] = p;
    if (tx == 0) {
        float s = fcb[0];
        #pragma unroll
        for (int h = 0; h < NH; ++h) s += bias[h] * fcW[h];
        g_const = s;
    }
}

// ---------------------------------------------------------------------------
// K2: degree histogram (blocks 0..NEB-1) fused with streaming ydot (blocks
// NEB..NEB+NYB-1). The two families touch disjoint state and neither depends
// on the other: ydot stores RAW y (dinv applied downstream) and zero-inits
// g_acc for the scatter. deg starts at 0 (k_out self-clean / zero-init).
// ---------------------------------------------------------------------------
__global__ void k_ydot_hist(const float* __restrict__ x,
                            const int* __restrict__ dst) {
    const int tx = threadIdx.x;
    if (blockIdx.x < NEB) {
        int e = blockIdx.x * 256 + tx;
        atomicAdd(&g_deg[__ldg(&dst[e])], 1);
        return;
    }
    const int t0 = (blockIdx.x - NEB) * 1024 + tx;       // < NY
    const float4* xp = reinterpret_cast<const float4*>(x);
    // 4 independent loads front-loaded for MLP
    float4 a0 = __ldcs(&xp[t0]);
    float4 a1 = __ldcs(&xp[t0 + 256]);
    float4 a2 = __ldcs(&xp[t0 + 512]);
    float4 a3 = __ldcs(&xp[t0 + 768]);
    float4 vv = reinterpret_cast<const float4*>(g_v)[tx & 7];

    float p0 = a0.x * vv.x + a0.y * vv.y + a0.z * vv.z + a0.w * vv.w;
    float p1 = a1.x * vv.x + a1.y * vv.y + a1.z * vv.z + a1.w * vv.w;
    float p2 = a2.x * vv.x + a2.y * vv.y + a2.z * vv.z + a2.w * vv.w;
    float p3 = a3.x * vv.x + a3.y * vv.y + a3.z * vv.z + a3.w * vv.w;
    #pragma unroll
    for (int o = 1; o <= 4; o <<= 1) {
        p0 += __shfl_xor_sync(0xFFFFFFFFu, p0, o);
        p1 += __shfl_xor_sync(0xFFFFFFFFu, p1, o);
        p2 += __shfl_xor_sync(0xFFFFFFFFu, p2, o);
        p3 += __shfl_xor_sync(0xFFFFFFFFu, p3, o);
    }

    if ((tx & 7) == 0) {
        #pragma unroll
        for (int u = 0; u < 4; ++u) {
            int t = t0 + u * 256;
            float p = (u == 0) ? p0 : (u == 1) ? p1 : (u == 2) ? p2 : p3;
            int f = t >> 3;             // row index = b*NZ + z
            int b = f / NZ;
            int z = f - b * NZ;
            g_y[z * NB + b]   = p;      // RAW y (no deg dependency)
            g_acc[z * NB + b] = 0.f;    // zero-init acc for the scatter
        }
    }
}

// ---------------------------------------------------------------------------
// K3: edge scatter with source normalization:
//   acc4[d*8+q] += rsqrt(deg[s]+1) * y4[s*8+q]
// 8 threads per edge, 2 edges/thread. deg is 16KB L2-resident (4 distinct
// addresses per warp-load); REDs are fire-and-forget so the deg latency is
// hidden by 1000 blocks of MLP.
// ---------------------------------------------------------------------------
__global__ void k_scatter(const int* __restrict__ src,
                          const int* __restrict__ dst) {
    int t0 = blockIdx.x * 512 + threadIdx.x;   // t = e*8 + q
    int t1 = t0 + 256;
    int e0 = t0 >> 3, q0 = t0 & 7;
    int e1 = t1 >> 3, q1 = t1 & 7;
    int s0 = __ldg(&src[e0]);
    int d0 = __ldg(&dst[e0]);
    int s1 = __ldg(&src[e1]);
    int d1 = __ldg(&dst[e1]);
    float dv0 = rsqrtf((float)(g_deg[s0] + 1));
    float dv1 = rsqrtf((float)(g_deg[s1] + 1));
    float4 y0 = reinterpret_cast<const float4*>(g_y)[s0 * 8 + q0];
    float4 y1 = reinterpret_cast<const float4*>(g_y)[s1 * 8 + q1];
    float4 m0 = make_float4(dv0 * y0.x, dv0 * y0.y, dv0 * y0.z, dv0 * y0.w);
    float4 m1 = make_float4(dv1 * y1.x, dv1 * y1.y, dv1 * y1.z, dv1 * y1.w);
    atomicAdd(&reinterpret_cast<float4*>(g_acc)[d0 * 8 + q0], m0);
    atomicAdd(&reinterpret_cast<float4*>(g_acc)[d1 * 8 + q1], m1);
}

// ---------------------------------------------------------------------------
// K4: out[b][z] = dinv_z * (acc[z][b] + dinv_z * y[z][b]) + const.
// 125 blocks x 256 threads, 32x33 tile, float4 everywhere.
// Self-cleans g_deg (acc is re-zeroed by k_ydot_hist next execution).
// ---------------------------------------------------------------------------
__global__ void k_out(float* __restrict__ out) {
    __shared__ float tile[32][33];
    const int tx = threadIdx.x;
    const int zb = blockIdx.x * 32;           // NZ % 32 == 0 (4000 = 125*32)

    // read side: thread (zi = tx>>3, q = tx&7) handles float4 q of row zb+zi
    int zi = tx >> 3;
    int q  = tx & 7;
    int z  = zb + zi;
    int ridx = z * 8 + q;                     // float4 index into acc/y rows
    float dinv = rsqrtf((float)(g_deg[z] + 1));   // broadcast among 8 threads
    float4 a4 = reinterpret_cast<const float4*>(g_acc)[ridx];
    float4 y4 = reinterpret_cast<const float4*>(g_y)[ridx];
    tile[zi][q * 4 + 0] = dinv * (a4.x + dinv * y4.x);
    tile[zi][q * 4 + 1] = dinv * (a4.y + dinv * y4.y);
    tile[zi][q * 4 + 2] = dinv * (a4.z + dinv * y4.z);
    tile[zi][q * 4 + 3] = dinv * (a4.w + dinv * y4.w);
    __syncthreads();

    // self-clean deg (all reads happened before the sync)
    if (tx < 32) g_deg[zb + tx] = 0;

    // write side: thread (b = tx>>3, zq = tx&7) writes out[b][zb+4zq .. +3]
    int b  = tx >> 3;
    int zq = tx & 7;
    float c = g_const;
    float4 o;
    o.x = tile[zq * 4 + 0][b] + c;
    o.y = tile[zq * 4 + 1][b] + c;
    o.z = tile[zq * 4 + 2][b] + c;
    o.w = tile[zq * 4 + 3][b] + c;
    reinterpret_cast<float4*>(out)[((size_t)b * NZ + zb) / 4 + zq] = o;
}

// ---------------------------------------------------------------------------
extern "C" void kernel_launch(void* const* d_in, const int* in_sizes, int n_in,
                              void* d_out, int out_size) {
    const float* x    = (const float*)d_in[0];   // [32,4000,32]
    const int*   ei   = (const int*)  d_in[1];   // [2,64000]
    const float* W    = (const float*)d_in[2];   // [32,64]
    const float* bias = (const float*)d_in[3];   // [64]
    const float* fcW  = (const float*)d_in[4];   // [64]
    const float* fcb  = (const float*)d_in[5];   // [1]
    float* out = (float*)d_out;                  // [32,4000]

    const int* src = ei;
    const int* dst = ei + NE;

    k_v<<<1, 256>>>(W, bias, fcW, fcb);
    k_ydot_hist<<<NEB + NYB, 256>>>(x, dst);
    k_scatter<<<NSB, 256>>>(src, dst);
    k_out<<<NZ / 32, 256>>>(out);
}